// round 11
// baseline (speedup 1.0000x reference)
#include <cuda_runtime.h>
#include <cuda_bf16.h>
#include <cuda_fp16.h>
#include <math.h>
#include <cstdint>
#include <cstddef>

#define NN 2048
#define CN 256
#define XP 4224          // padded column stride (33*128)
#define FBC 4160         // real columns = 65*64
#define SSTRIDE 131072   // NN*64
#define ELLW 128

// ---------------- scratch (device globals) ---------------------------------
__device__ __nv_bfloat16 g_x0h[(size_t)NN * XP];   // x0 hi plane (GEMM)
__device__ __nv_bfloat16 g_x0l[(size_t)NN * XP];   // x0 lo plane (GEMM)
__device__ __half        g_x0fA[(size_t)NN * XP];  // x0 fp16 plane, pass 0 (SpMM)
__device__ __half        g_x0fB[(size_t)NN * XP];  // x0 fp16 plane, pass 1 (SpMM)
__device__ __nv_bfloat16 g_fch[(size_t)CN * XP];
__device__ __nv_bfloat16 g_fcl[(size_t)CN * XP];
__device__ __nv_bfloat16 g_afch[(size_t)CN * NN];
__device__ __nv_bfloat16 g_afcl[(size_t)CN * NN];
__device__ __nv_bfloat16 g_afcth[(size_t)NN * CN];
__device__ __nv_bfloat16 g_afctl[(size_t)NN * CN];
__device__ float    g_x1[(size_t)NN * XP];
__device__ float    g_u[(size_t)64 * SSTRIDE];
__device__ unsigned short g_cols[(size_t)NN * ELLW];
__device__ float    g_wts[(size_t)NN * ELLW];
__device__ int      g_nnz[NN];

__device__ __forceinline__ float sigf(float x) { return 1.0f / (1.0f + expf(-x)); }
__device__ __forceinline__ void splitf(float v, __nv_bfloat16& h, __nv_bfloat16& l) {
    h = __float2bfloat16(v);
    l = __float2bfloat16(v - __bfloat162float(h));
}
__device__ __forceinline__ uint32_t smem_u32(const void* p) {
    uint32_t a;
    asm("{ .reg .u64 t; cvta.to.shared.u64 t, %1; cvt.u32.u64 %0, t; }" : "=r"(a) : "l"(p));
    return a;
}
__device__ __forceinline__ void cpasync16(uint32_t s, const void* g) {
    asm volatile("cp.async.cg.shared.global [%0], [%1], 16;" :: "r"(s), "l"(g));
}
#define CP_COMMIT() asm volatile("cp.async.commit_group;" ::: "memory")
template<int N> __device__ __forceinline__ void cp_wait() {
    asm volatile("cp.async.wait_group %0;" :: "n"(N) : "memory");
}

__device__ __forceinline__ void ldsm4(uint32_t* r, uint32_t a) {
    asm volatile("ldmatrix.sync.aligned.m8n8.x4.shared.b16 {%0,%1,%2,%3}, [%4];"
        : "=r"(r[0]), "=r"(r[1]), "=r"(r[2]), "=r"(r[3]) : "r"(a));
}
__device__ __forceinline__ void ldsm4t(uint32_t* r, uint32_t a) {
    asm volatile("ldmatrix.sync.aligned.m8n8.x4.trans.shared.b16 {%0,%1,%2,%3}, [%4];"
        : "=r"(r[0]), "=r"(r[1]), "=r"(r[2]), "=r"(r[3]) : "r"(a));
}
__device__ __forceinline__ void mma_bf16(float* c, const uint32_t* a, uint32_t b0, uint32_t b1) {
    asm volatile("mma.sync.aligned.m16n8k16.row.col.f32.bf16.bf16.f32 "
        "{%0,%1,%2,%3}, {%4,%5,%6,%7}, {%8,%9}, {%0,%1,%2,%3};"
        : "+f"(c[0]), "+f"(c[1]), "+f"(c[2]), "+f"(c[3])
        : "r"(a[0]), "r"(a[1]), "r"(a[2]), "r"(a[3]), "r"(b0), "r"(b1));
}

// ---------------- packed f32x2 FMA (sm_100+ base ISA) -----------------------
__device__ __forceinline__ void fma2(uint64_t& acc, uint64_t a, uint64_t b) {
    asm("fma.rn.f32x2 %0, %1, %2, %0;" : "+l"(acc) : "l"(a), "l"(b));
}
__device__ __forceinline__ uint64_t packf2(float lo, float hi) {
    uint64_t r;
    asm("mov.b64 %0, {%1, %2};" : "=l"(r) : "f"(lo), "f"(hi));
    return r;
}
__device__ __forceinline__ void unpackf2(uint64_t v, float& lo, float& hi) {
    asm("mov.b64 {%0, %1}, %2;" : "=f"(lo), "=f"(hi) : "l"(v));
}

// ---------------------------------------------------------------------------
// setup_kernel: build_ell (block compaction scan) + weight convert + pack_x0
// ---------------------------------------------------------------------------
__global__ __launch_bounds__(256) void setup_kernel(const float* __restrict__ adj,
    const float* __restrict__ afc, const float* __restrict__ afct,
    const float* __restrict__ inputs, const float* __restrict__ state)
{
    __shared__ float tile[64 * 65];
    __shared__ int wsum[8];
    const int n = blockIdx.x, t = threadIdx.x;
    const int lane = t & 31, wid = t >> 5;

    // --- weight convert (1 elem/thread) ---
    {
        int i = n * 256 + t;
        __nv_bfloat16 h, l;
        splitf(afc[i],  h, l); g_afch[i]  = h; g_afcl[i]  = l;
        splitf(afct[i], h, l); g_afcth[i] = h; g_afctl[i] = l;
    }

    // --- ELL compaction of adj row n ---
    const float* row = adj + (size_t)n * NN;
    float v[8];
    float4 p0 = *(const float4*)(row + t * 8);
    float4 p1 = *(const float4*)(row + t * 8 + 4);
    v[0] = p0.x; v[1] = p0.y; v[2] = p0.z; v[3] = p0.w;
    v[4] = p1.x; v[5] = p1.y; v[6] = p1.z; v[7] = p1.w;
    int cnt = 0;
#pragma unroll
    for (int q = 0; q < 8; q++) cnt += (v[q] != 0.0f);
    int inc = cnt;
#pragma unroll
    for (int off = 1; off < 32; off <<= 1) {
        int y = __shfl_up_sync(0xFFFFFFFFu, inc, off);
        if (lane >= off) inc += y;
    }
    if (lane == 31) wsum[wid] = inc;
    __syncthreads();
    int wbase = 0;
#pragma unroll
    for (int w = 0; w < 8; w++) wbase += (w < wid) ? wsum[w] : 0;
    int pos = wbase + inc - cnt;
#pragma unroll
    for (int q = 0; q < 8; q++) {
        if (v[q] != 0.0f) {
            if (pos < ELLW) {
                g_cols[(size_t)n * ELLW + pos] = (unsigned short)(t * 8 + q);
                g_wts[(size_t)n * ELLW + pos] = v[q];
            }
            pos++;
        }
    }
    if (t == 255) g_nnz[n] = (pos < ELLW) ? pos : ELLW;

    // --- pack x0 row n (3 planes; fp16 -> buffer A) ---
    for (int i = t; i < 4096; i += 256) {
        int b = i >> 6, u = i & 63;
        tile[b * 65 + u] = state[(size_t)b * SSTRIDE + n * 64 + u];
    }
    __syncthreads();
    __nv_bfloat16* rh = g_x0h + (size_t)n * XP;
    __nv_bfloat16* rl = g_x0l + (size_t)n * XP;
    __half*        rf = g_x0fA + (size_t)n * XP;
    if (t < 64) {
        float vv = inputs[t * NN + n];
        __nv_bfloat16 h, l; splitf(vv, h, l);
        rh[t] = h; rl[t] = l; rf[t] = __float2half(vv);
    }
    for (int i = t; i < 4096; i += 256) {
        int u = i >> 6, b = i & 63;
        float vv = tile[b * 65 + u];
        __nv_bfloat16 h, l; splitf(vv, h, l);
        rh[64 + i] = h; rl[64 + i] = l; rf[64 + i] = __float2half(vv);
    }
}

// ---------------------------------------------------------------------------
// gemm_mma<BM, BN, EPI, NS>: C(Mx4224) = A(MxK) @ B(Kx4224), split-3 bf16,
// NS-stage cp.async pipeline, one sync per chunk, loads before compute.
// EPI 0: write split planes (C0=hi, C1=lo); EPI 1: C0 = sigmoid fp32
// ---------------------------------------------------------------------------
template<int BM, int BN, int EPI, int NS>
__global__ __launch_bounds__(256, 2) void gemm_mma(
    const __nv_bfloat16* __restrict__ Ah, const __nv_bfloat16* __restrict__ Al,
    const __nv_bfloat16* __restrict__ Bh, const __nv_bfloat16* __restrict__ Bl,
    void* __restrict__ C0, void* __restrict__ C1, int K, int lda, int ldb)
{
    extern __shared__ char smem[];
    constexpr int ABYTES = BM * 128;
    constexpr int BCH    = BN / 8;          // 16B chunks per B row
    constexpr int BROW   = BN * 2;          // bytes per B k-row (one plane)
    constexpr int BPLANE = 32 * BROW;
    constexpr int STAGE  = ABYTES + 2 * BPLANE;
    constexpr int WARPS_M = BM / 32;
    constexpr int WARPS_N = 8 / WARPS_M;
    constexpr int WNT = BN / WARPS_N;
    constexpr int NB = WNT / 8, NG = WNT / 16;

    const uint32_t sb = smem_u32(smem);
    const int t = threadIdx.x, lane = t & 31, wid = t >> 5;
    const int wm = wid % WARPS_M, wn = wid / WARPS_M;
    const int m0 = blockIdx.y * BM, n0 = blockIdx.x * BN;

    float c[2][NB][4];
#pragma unroll
    for (int s = 0; s < 2; s++)
#pragma unroll
        for (int nb = 0; nb < NB; nb++)
#pragma unroll
            for (int k = 0; k < 4; k++) c[s][nb][k] = 0.f;

    auto load_stage = [&](int st, int k0) {
        uint32_t sA = sb + st * STAGE;
        uint32_t sB = sA + ABYTES;
#pragma unroll
        for (int it = 0; it < BM * 8 / 256; it++) {
            int idx = t + it * 256;
            int r = idx >> 3, ch = idx & 7;
            const __nv_bfloat16* src = (ch < 4 ? Ah : Al)
                + (size_t)(m0 + r) * lda + k0 + (ch & 3) * 8;
            cpasync16(sA + r * 128 + ((ch ^ (r & 7)) * 16), src);
        }
#pragma unroll
        for (int it = 0; it < 2 * 32 * BCH / 256; it++) {
            int idx = t + it * 256;
            int p = idx / (32 * BCH), rem = idx % (32 * BCH);
            int k = rem / BCH, ch = rem % BCH;
            const __nv_bfloat16* src = (p ? Bl : Bh)
                + (size_t)(k0 + k) * ldb + n0 + ch * 8;
            cpasync16(sB + p * BPLANE + k * BROW + ((ch ^ (k & 7)) * 16), src);
        }
    };

    const int klb = ((lane >> 3) & 1) * 8 + (lane & 7);
    const int nchb = wn * (WNT / 8) + (lane >> 4);

    const int NC = K / 32;
#pragma unroll
    for (int s = 0; s < NS - 1; s++) {
        if (s < NC) load_stage(s, s * 32);
        CP_COMMIT();
    }
    for (int cc = 0; cc < NC; cc++) {
        cp_wait<NS - 2>();
        __syncthreads();
        int nxt = cc + NS - 1;
        if (nxt < NC) load_stage(nxt % NS, nxt * 32);
        CP_COMMIT();

        uint32_t sA = sb + (cc % NS) * STAGE;
        uint32_t sB = sA + ABYTES;
#pragma unroll
        for (int c16 = 0; c16 < 2; c16++) {
            uint32_t ah[2][4], al[2][4];
#pragma unroll
            for (int s = 0; s < 2; s++) {
                int r = wm * 32 + s * 16 + (lane & 15);
                int lc = c16 * 2 + (lane >> 4);
                ldsm4(ah[s], sA + r * 128 + ((lc ^ (r & 7)) * 16));
                ldsm4(al[s], sA + r * 128 + (((lc + 4) ^ (r & 7)) * 16));
            }
#pragma unroll
            for (int g = 0; g < NG; g++) {
                int k = c16 * 16 + klb;
                int nch = nchb + g * 2;
                uint32_t boff = sB + k * BROW + ((nch ^ (k & 7)) * 16);
                uint32_t bh[4], bl[4];
                ldsm4t(bh, boff);
                ldsm4t(bl, boff + BPLANE);
#pragma unroll
                for (int s = 0; s < 2; s++) {
                    mma_bf16(c[s][2 * g],     ah[s], bh[0], bh[1]);
                    mma_bf16(c[s][2 * g + 1], ah[s], bh[2], bh[3]);
                    mma_bf16(c[s][2 * g],     ah[s], bl[0], bl[1]);
                    mma_bf16(c[s][2 * g + 1], ah[s], bl[2], bl[3]);
                    mma_bf16(c[s][2 * g],     al[s], bh[0], bh[1]);
                    mma_bf16(c[s][2 * g + 1], al[s], bh[2], bh[3]);
                }
            }
        }
    }

    const int gi = lane >> 2, ti = lane & 3;
#pragma unroll
    for (int s = 0; s < 2; s++) {
        int row = m0 + wm * 32 + s * 16 + gi;
#pragma unroll
        for (int nb = 0; nb < NB; nb++) {
            int col = n0 + wn * WNT + nb * 8 + ti * 2;
#pragma unroll
            for (int half = 0; half < 2; half++) {
                int rr = row + half * 8;
                float v0 = c[s][nb][half * 2], v1 = c[s][nb][half * 2 + 1];
                if (EPI == 0) {
                    __nv_bfloat16 h0, l0, h1, l1;
                    splitf(v0, h0, l0); splitf(v1, h1, l1);
                    uint32_t hv = (uint32_t)__bfloat16_as_ushort(h0)
                                | ((uint32_t)__bfloat16_as_ushort(h1) << 16);
                    uint32_t lv = (uint32_t)__bfloat16_as_ushort(l0)
                                | ((uint32_t)__bfloat16_as_ushort(l1) << 16);
                    *(uint32_t*)((__nv_bfloat16*)C0 + (size_t)rr * XP + col) = hv;
                    *(uint32_t*)((__nv_bfloat16*)C1 + (size_t)rr * XP + col) = lv;
                } else {
                    *(float2*)((float*)C0 + (size_t)rr * XP + col) =
                        make_float2(sigf(v0), sigf(v1));
                }
            }
        }
    }
}

// ---------------------------------------------------------------------------
// spmm prelude: xs[0..FBC) = x1[n,:] + sum_e w * x0f_src[cols[e], :]
// ---------------------------------------------------------------------------
__device__ __forceinline__ void spmm_into_smem(int n, float* xs, const __half* x0f,
    const unsigned short* sc, const float* sw, int nnz, int t)
{
    const float* xrow = g_x1 + (size_t)n * XP;
#pragma unroll
    for (int sub = 0; sub < 3; sub++) {
        int ch = sub * 256 + t;
        if (ch < 520) {
            const int jf = ch * 8;
            float acc[8];
#pragma unroll
            for (int q = 0; q < 8; q++) acc[q] = 0.f;
            int e = 0;
            for (; e + 1 < nnz; e += 2) {
                uint4 a = *(const uint4*)(x0f + (size_t)sc[e] * XP + jf);
                uint4 b = *(const uint4*)(x0f + (size_t)sc[e + 1] * XP + jf);
                float w0 = sw[e], w1 = sw[e + 1];
                const uint32_t* ua = &a.x;
                const uint32_t* ub = &b.x;
#pragma unroll
                for (int q = 0; q < 4; q++) {
                    float2 fa = __half22float2(*(const __half2*)&ua[q]);
                    float2 fb = __half22float2(*(const __half2*)&ub[q]);
                    acc[2 * q]     += w0 * fa.x + w1 * fb.x;
                    acc[2 * q + 1] += w0 * fa.y + w1 * fb.y;
                }
            }
            if (e < nnz) {
                uint4 a = *(const uint4*)(x0f + (size_t)sc[e] * XP + jf);
                float w0 = sw[e];
                const uint32_t* ua = &a.x;
#pragma unroll
                for (int q = 0; q < 4; q++) {
                    float2 fa = __half22float2(*(const __half2*)&ua[q]);
                    acc[2 * q]     += w0 * fa.x;
                    acc[2 * q + 1] += w0 * fa.y;
                }
            }
            float4 g0 = *(const float4*)(xrow + jf);
            float4 g1 = *(const float4*)(xrow + jf + 4);
            xs[jf + 0] = g0.x + acc[0]; xs[jf + 1] = g0.y + acc[1];
            xs[jf + 2] = g0.z + acc[2]; xs[jf + 3] = g0.w + acc[3];
            xs[jf + 4] = g1.x + acc[4]; xs[jf + 5] = g1.y + acc[5];
            xs[jf + 6] = g1.z + acc[6]; xs[jf + 7] = g1.w + acc[7];
        }
    }
}

// ---------------------------------------------------------------------------
// gate (fused spmm, gathers plane A): r,u = sigmoid(x1tot[n]·w0 + b0);
// packed f32x2 FMA; writes split(r*state) into x0 planes + fp16 plane B, u to g_u
// ---------------------------------------------------------------------------
__global__ __launch_bounds__(256)
void gate_kernel(const float* __restrict__ inputs, const float* __restrict__ state,
                 const float* __restrict__ w0, const float* __restrict__ b0)
{
    __shared__ float xs[FBC];
    __shared__ float st[64 * 65];
    __shared__ unsigned short sc[ELLW];
    __shared__ float sw[ELLW];
    const int n = blockIdx.x, t = threadIdx.x;
    if (t < ELLW) {
        sc[t] = g_cols[(size_t)n * ELLW + t];
        sw[t] = g_wts[(size_t)n * ELLW + t];
    }
    __syncthreads();
    const int nnz = g_nnz[n];
    spmm_into_smem(n, xs, g_x0fA, sc, sw, nnz, t);
    __syncthreads();

    const int jt = t & 15, bt = t >> 4;
    const int j0 = jt * 8, b0v = bt * 4;
    uint64_t acc2[4][4];
#pragma unroll
    for (int i = 0; i < 4; i++)
#pragma unroll
        for (int k = 0; k < 4; k++) acc2[i][k] = 0ull;

    for (int f = 0; f < 65; f++) {
        float4 wa = __ldg((const float4*)(w0 + f * 128 + j0));
        float4 wb = __ldg((const float4*)(w0 + f * 128 + j0 + 4));
        uint64_t w2[4] = { packf2(wa.x, wa.y), packf2(wa.z, wa.w),
                           packf2(wb.x, wb.y), packf2(wb.z, wb.w) };
#pragma unroll
        for (int i = 0; i < 4; i++) {
            float xv = xs[f * 64 + b0v + i];
            uint64_t x2 = packf2(xv, xv);
#pragma unroll
            for (int k = 0; k < 4; k++) fma2(acc2[i][k], x2, w2[k]);
        }
    }
    float acc[4][8];
#pragma unroll
    for (int i = 0; i < 4; i++)
#pragma unroll
        for (int k = 0; k < 4; k++)
            unpackf2(acc2[i][k], acc[i][2 * k], acc[i][2 * k + 1]);

    float bb[8];
#pragma unroll
    for (int k = 0; k < 8; k++) bb[k] = __ldg(b0 + j0 + k);

    __nv_bfloat16* rh = g_x0h + (size_t)n * XP;
    __nv_bfloat16* rl = g_x0l + (size_t)n * XP;
    __half*        rf = g_x0fB + (size_t)n * XP;

    if (jt < 8) {
#pragma unroll
        for (int i = 0; i < 4; i++)
#pragma unroll
            for (int k = 0; k < 8; k++) {
                int j = j0 + k, b = b0v + i;
                float r = sigf(acc[i][k] + bb[k]);
                st[b * 65 + j] = r * __ldg(state + (size_t)b * SSTRIDE + n * 64 + j);
            }
    }
    __syncthreads();
    for (int i = t; i < 4096; i += 256) {
        int j = i >> 6, b = i & 63;
        float v = st[b * 65 + j];
        __nv_bfloat16 h, l; splitf(v, h, l);
        rh[64 + i] = h; rl[64 + i] = l; rf[64 + i] = __float2half(v);
    }
    if (t < 64) {
        float v = inputs[t * NN + n];
        __nv_bfloat16 h, l; splitf(v, h, l);
        rh[t] = h; rl[t] = l; rf[t] = __float2half(v);
    }
    __syncthreads();

    if (jt >= 8) {
#pragma unroll
        for (int i = 0; i < 4; i++)
#pragma unroll
            for (int k = 0; k < 8; k++) {
                int ju = j0 - 64 + k, b = b0v + i;
                st[b * 65 + ju] = sigf(acc[i][k] + bb[k]);
            }
    }
    __syncthreads();
    for (int i = t; i < 4096; i += 256) {
        int b = i >> 6, ju = i & 63;
        g_u[(size_t)b * SSTRIDE + n * 64 + ju] = st[b * 65 + ju];
    }
}

// ---------------------------------------------------------------------------
// candidate + combine (fused spmm, gathers plane B), packed f32x2 FMA:
// c = tanh(x1tot·w1 + b1); out = u*state + (1-u)*c
// ---------------------------------------------------------------------------
__global__ __launch_bounds__(256)
void cand_kernel(const float* __restrict__ state, const float* __restrict__ w1,
                 const float* __restrict__ b1, float* __restrict__ out)
{
    __shared__ float xs[FBC];
    __shared__ float st[64 * 65];
    __shared__ unsigned short sc[ELLW];
    __shared__ float sw[ELLW];
    const int n = blockIdx.x, t = threadIdx.x;
    if (t < ELLW) {
        sc[t] = g_cols[(size_t)n * ELLW + t];
        sw[t] = g_wts[(size_t)n * ELLW + t];
    }
    __syncthreads();
    const int nnz = g_nnz[n];
    spmm_into_smem(n, xs, g_x0fB, sc, sw, nnz, t);
    __syncthreads();

    const int jt = t & 15, bt = t >> 4;
    const int j0 = jt * 4, b0v = bt * 4;
    uint64_t acc2[4][2];
#pragma unroll
    for (int i = 0; i < 4; i++) { acc2[i][0] = 0ull; acc2[i][1] = 0ull; }

    for (int f = 0; f < 65; f++) {
        float4 w4 = __ldg((const float4*)(w1 + f * 64 + j0));
        uint64_t w2[2] = { packf2(w4.x, w4.y), packf2(w4.z, w4.w) };
#pragma unroll
        for (int i = 0; i < 4; i++) {
            float xv = xs[f * 64 + b0v + i];
            uint64_t x2 = packf2(xv, xv);
            fma2(acc2[i][0], x2, w2[0]);
            fma2(acc2[i][1], x2, w2[1]);
        }
    }
    float acc[4][4];
#pragma unroll
    for (int i = 0; i < 4; i++) {
        unpackf2(acc2[i][0], acc[i][0], acc[i][1]);
        unpackf2(acc2[i][1], acc[i][2], acc[i][3]);
    }
#pragma unroll
    for (int i = 0; i < 4; i++)
#pragma unroll
        for (int k = 0; k < 4; k++) {
            int j = j0 + k, b = b0v + i;
            st[b * 65 + j] = tanhf(acc[i][k] + __ldg(b1 + j));
        }
    __syncthreads();
    for (int i = t; i < 4096; i += 256) {
        int b = i >> 6, j = i & 63;
        size_t addr = (size_t)b * SSTRIDE + n * 64 + j;
        float u = g_u[addr], s = state[addr];
        out[addr] = u * s + (1.f - u) * st[b * 65 + j];
    }
}

// ---------------------------------------------------------------------------
extern "C" void kernel_launch(void* const* d_in, const int* in_sizes, int n_in,
                              void* d_out, int out_size)
{
    const float* inputs = (const float*)d_in[0];
    const float* state  = (const float*)d_in[1];
    const float* adj    = (const float*)d_in[2];
    const float* afc    = (const float*)d_in[4];
    const float* afct   = (const float*)d_in[5];
    const float* w0     = (const float*)d_in[6];
    const float* b0     = (const float*)d_in[7];
    const float* w1     = (const float*)d_in[8];
    const float* b1     = (const float*)d_in[9];
    float* out = (float*)d_out;

    __nv_bfloat16 *x0h, *x0l, *fch, *fcl, *afch, *afcl, *afcth, *afctl;
    float* x1;
    cudaGetSymbolAddress((void**)&x0h,   g_x0h);
    cudaGetSymbolAddress((void**)&x0l,   g_x0l);
    cudaGetSymbolAddress((void**)&fch,   g_fch);
    cudaGetSymbolAddress((void**)&fcl,   g_fcl);
    cudaGetSymbolAddress((void**)&afch,  g_afch);
    cudaGetSymbolAddress((void**)&afcl,  g_afcl);
    cudaGetSymbolAddress((void**)&afcth, g_afcth);
    cudaGetSymbolAddress((void**)&afctl, g_afctl);
    cudaGetSymbolAddress((void**)&x1,    g_x1);

    const int SM_FC  = 6 * (64 * 128 + 2 * 32 * 128);     // 98304 (6-stage, BN=64)
    const int SM_BIG = 3 * (128 * 128 + 2 * 32 * 256);    // 98304 (3-stage, BN=128)
    cudaFuncSetAttribute(gemm_mma<64, 64, 0, 6>,   cudaFuncAttributeMaxDynamicSharedMemorySize, SM_FC);
    cudaFuncSetAttribute(gemm_mma<128, 128, 1, 3>, cudaFuncAttributeMaxDynamicSharedMemorySize, SM_BIG);

    dim3 blk(256);
    setup_kernel<<<NN, blk>>>(adj, afc, afct, inputs, state);

    for (int pass = 0; pass < 2; pass++) {
        // x0fc = afc @ x0   (256 x 4224, K=2048) -> split planes
        gemm_mma<64, 64, 0, 6><<<dim3(XP / 64, CN / 64), blk, SM_FC>>>(
            afch, afcl, x0h, x0l, fch, fcl, NN, NN, XP);
        // x1 = sigmoid(afct @ x0fc)   (2048 x 4224, K=256) -> fp32
        gemm_mma<128, 128, 1, 3><<<dim3(XP / 128, NN / 128), blk, SM_BIG>>>(
            afcth, afctl, fch, fcl, x1, nullptr, CN, CN, XP);
        // spmm fused into gate/cand (double-buffered fp16 planes: A -> B)
        if (pass == 0)
            gate_kernel<<<NN, blk>>>(inputs, state, w0, b0);
        else
            cand_kernel<<<NN, blk>>>(state, w1, b1, out);
    }
}